// round 13
// baseline (speedup 1.0000x reference)
#include <cuda_runtime.h>

// Local cost volume (SpatialCorrelationSampler, kernel_size=1, patch 9x9):
// out[b, p, y, x] = sum_c t1[b,c,y,x] * t2[b,c,y+di,x+dj],  p=(di+4)*9+(dj+4)
// t1,t2 [4,128,128,256] f32 -> out [4,81,128,256] f32.
//
// CTA = 96 threads = 3 warps: one x-tile of 128 px, three di rows.
// R12 change: di-group is folded into the FASTEST grid bits so the three
// di-group CTAs of one (y, x-tile) run in the same wave on adjacent SMs ->
// t1 read once from L2 instead of 3x from DRAM, t2 shared across adjacent-y
// CTAs. (R11 had di-group in blockIdx.y: 3 temporally separated bands each
// re-reading 128 MB -> measured 383 MB DRAM.)
// 4 px/lane, packed fma.rn.f32x2, 2-stage cp.async, 10 CTAs/SM.

#define CH 128
#define HH 128
#define WW 256
#define MD 4
#define DD 9
#define NDI 3             // di rows per CTA
#define CC 4
#define XT 128
#define T2C 136           // 34 granules of 4 floats
#define HW (HH*WW)
#define NTHREADS 96
#define NCHUNK 32
#define STAGES 2

#define T1_STG (CC*XT)          // 512 floats
#define T2_STG (CC*NDI*T2C)     // 1632 floats
#define SMEM_BYTES (STAGES*(T1_STG+T2_STG)*4)   // 17,152 B

typedef unsigned long long u64;

__device__ __forceinline__ u64 pk(float lo, float hi) {
    u64 r; asm("mov.b64 %0, {%1,%2};" : "=l"(r) : "f"(lo), "f"(hi)); return r;
}
__device__ __forceinline__ void fma2(u64 &d, u64 a, u64 b) {
    asm("fma.rn.f32x2 %0, %1, %2, %0;" : "+l"(d) : "l"(a), "l"(b));
}
__device__ __forceinline__ float2 upk(u64 v) {
    float lo, hi; asm("mov.b64 {%0,%1}, %2;" : "=f"(lo), "=f"(hi) : "l"(v));
    return make_float2(lo, hi);
}
__device__ __forceinline__ void cpasync16(unsigned smem_addr, const void* gptr) {
    asm volatile("cp.async.cg.shared.global [%0], [%1], 16;" ::
                 "r"(smem_addr), "l"(gptr));
}

__global__ __launch_bounds__(NTHREADS, 10)
void corr_volume_kernel(const float* __restrict__ t1,
                        const float* __restrict__ t2,
                        float* __restrict__ out)
{
    extern __shared__ float sm[];
    float* s_t1 = sm;                       // [STAGES][CC][XT]
    float* s_t2 = sm + STAGES * T1_STG;     // [STAGES][CC][NDI][T2C]

    const int tid   = threadIdx.x;
    const int wid   = tid >> 5;             // 0..2 within CTA
    const int lane  = tid & 31;

    // bid = (((batch*HH + y)*2 + xt)*3 + dig)  -- dig fastest
    const int blk  = blockIdx.x;            // 0..3071
    const int dig  = blk - (blk / 3) * 3;   // di group 0..2
    const int rest = blk / 3;
    const int xt    = rest & 1;
    const int y     = (rest >> 1) & (HH - 1);
    const int batch = rest >> 8;
    const int x0    = xt * XT;
    const int di    = dig * NDI + wid;      // 0..8

    const int gy = y + di - MD;
    const bool vrow = (unsigned)gy < (unsigned)HH;     // warp-uniform

    // halo: smem col j holds gx = x0 + j - 4. valid granules h in [lo, lo+33),
    // one pad granule per row at hpad.
    const int lo   = (xt == 0) ? 1 : 0;
    const int hpad = (xt == 0) ? 0 : 33;

    // ---- one-time zero of constant pad regions (both stages) ----
    // t2 row (cc, wid) is written AND read only by warp wid.
    {
        const float4 z = make_float4(0.f, 0.f, 0.f, 0.f);
        #pragma unroll
        for (int st = 0; st < STAGES; st++)
            #pragma unroll
            for (int cc = 0; cc < CC; cc++) {
                float* row = s_t2 + (size_t)st * T2_STG + (cc * NDI + wid) * T2C;
                if (vrow) {
                    if (lane == 0) *(float4*)&row[4 * hpad] = z;
                } else {
                    *(float4*)&row[4 * lane] = z;               // granules 0..31
                    if (lane < 2) *(float4*)&row[4 * (32 + lane)] = z;
                }
            }
    }

    u64 acc[DD][2];
    #pragma unroll
    for (int d = 0; d < DD; d++) { acc[d][0] = 0ull; acc[d][1] = 0ull; }

    const int xl = lane * 4;

    // ---- copy target addresses (stage 0) ----
    // t2: warp fills its own row; lane -> granule lo+lane, lane0 also lo+32.
    const unsigned t2b = (unsigned)__cvta_generic_to_shared(s_t2);
    const unsigned t1b = (unsigned)__cvta_generic_to_shared(s_t1);
    const unsigned t2d1 = t2b + (unsigned)(wid * T2C + 4 * (lo + lane)) * 4;
    const unsigned t2d2 = t2b + (unsigned)(wid * T2C + 4 * (lo + 32)) * 4;
    const float* t2src = t2 + (size_t)batch * CH * HW
                            + (size_t)(vrow ? gy : 0) * WW + (x0 - 4 + 4 * lo);
    // t1: thread tid fills granule g=tid (cc=g>>5), tid<32 also g2=96+tid (cc=3).
    const int g1 = tid, g2 = 96 + tid;
    const unsigned t1d1 = t1b + (unsigned)((g1 >> 5) * XT + 4 * (g1 & 31)) * 4;
    const unsigned t1d2 = t1b + (unsigned)((g2 >> 5) * XT + 4 * (g2 & 31)) * 4;
    const float* t1row = t1 + (size_t)batch * CH * HW + (size_t)y * WW + x0;
    const float* t1s1 = t1row + (size_t)(g1 >> 5) * HW + 4 * (g1 & 31);
    const float* t1s2 = t1row + (size_t)(g2 >> 5) * HW + 4 * (g2 & 31);

    auto issue = [&](int chunk) {
        const int c0 = chunk * CC;
        const unsigned stoff = (chunk & 1) ? 1u : 0u;
        if (vrow) {
            const float* src = t2src + (size_t)c0 * HW;
            const unsigned so = stoff * (T2_STG * 4);
            #pragma unroll
            for (int cc = 0; cc < CC; cc++) {
                const unsigned co = so + (unsigned)(cc * (NDI * T2C)) * 4;
                cpasync16(t2d1 + co, src + (size_t)cc * HW + 4 * lane);
                if (lane == 0) cpasync16(t2d2 + co, src + (size_t)cc * HW + 128);
            }
        }
        {
            const unsigned so = stoff * (T1_STG * 4);
            cpasync16(t1d1 + so, t1s1 + (size_t)c0 * HW);
            if (tid < 32) cpasync16(t1d2 + so, t1s2 + (size_t)c0 * HW);
        }
        asm volatile("cp.async.commit_group;");
    };

    issue(0);

    for (int it = 0; it < NCHUNK; it++) {
        const int st = it & 1;
        asm volatile("cp.async.wait_group 0;");
        __syncthreads();               // chunk `it` visible; other stage free
        if (it + 1 < NCHUNK) issue(it + 1);

        const float* b_t1 = s_t1 + (size_t)st * T1_STG;
        const float* b_t2 = s_t2 + (size_t)st * T2_STG;

        #pragma unroll
        for (int cc = 0; cc < CC; cc++) {
            float4 a = *(const float4*)&b_t1[cc * XT + xl];
            u64 A0 = pk(a.x, a.y), A1 = pk(a.z, a.w);

            const float* tr = &b_t2[(cc * NDI + wid) * T2C + xl];
            float4 v0 = *(const float4*)&tr[0];
            float4 v1 = *(const float4*)&tr[4];
            float4 v2 = *(const float4*)&tr[8];

            u64 P[6];
            P[0] = pk(v0.x, v0.y); P[1] = pk(v0.z, v0.w);
            P[2] = pk(v1.x, v1.y); P[3] = pk(v1.z, v1.w);
            P[4] = pk(v2.x, v2.y); P[5] = pk(v2.z, v2.w);
            u64 Q[5];
            Q[0] = pk(v0.y, v0.z); Q[1] = pk(v0.w, v1.x);
            Q[2] = pk(v1.y, v1.z); Q[3] = pk(v1.w, v2.x);
            Q[4] = pk(v2.y, v2.z);

            #pragma unroll
            for (int dj = 0; dj < DD; dj++) {
                const int h = dj >> 1;
                if ((dj & 1) == 0) {
                    fma2(acc[dj][0], A0, P[h + 0]);
                    fma2(acc[dj][1], A1, P[h + 1]);
                } else {
                    fma2(acc[dj][0], A0, Q[h + 0]);
                    fma2(acc[dj][1], A1, Q[h + 1]);
                }
            }
        }
    }

    // ---- write out: p = di*9 + dj ----
    size_t obase = (((size_t)batch * 81 + (size_t)di * DD) * HH + y) * WW + x0 + xl;
    #pragma unroll
    for (int dj = 0; dj < DD; dj++) {
        float2 p0 = upk(acc[dj][0]), p1 = upk(acc[dj][1]);
        *(float4*)&out[obase + (size_t)dj * HW] = make_float4(p0.x, p0.y, p1.x, p1.y);
    }
}

extern "C" void kernel_launch(void* const* d_in, const int* in_sizes, int n_in,
                              void* d_out, int out_size)
{
    const float* t1 = (const float*)d_in[0];
    const float* t2 = (const float*)d_in[1];
    float* out = (float*)d_out;
    cudaFuncSetAttribute(corr_volume_kernel,
                         cudaFuncAttributeMaxDynamicSharedMemorySize, SMEM_BYTES);
    corr_volume_kernel<<<2 * 4 * HH * (DD / NDI), NTHREADS, SMEM_BYTES>>>(t1, t2, out);
}